// round 14
// baseline (speedup 1.0000x reference)
#include <cuda_runtime.h>

#define EDIM 512
#define HDIM 256
#define QN   1024
#define SN   512
#define NSTEP 3

// ---------------- scratch (no allocations allowed) ----------------
__device__ float g_tmp[(QN + SN) * HDIM];   // hidden of encoder MLP
__device__ float g_enc[(QN + SN) * HDIM];   // q rows [0,1024), s rows [1024,1536)
__device__ float g_A[SN * HDIM];
__device__ float g_Bm[SN * HDIM];
__device__ float g_Hagg[SN * HDIM];
__device__ float g_hq[QN * HDIM];
__device__ float g_hs[SN * HDIM];
__device__ float g_rdenom[SN];
__device__ float g_flag[SN];

// ---------------- generic fp32 GEMM: C = A(MxK) @ B(KxN=256) ----------------
// 32x64 block tile, 512 threads, intra-block split-K (2 halves).
// WHOLE K-half staged in dynamic smem up front (one barrier), then pure
// LDS+FFMA with no barriers. 2x4 micro-tile.
// blockIdx.z selects between two argument sets (fused paired launches).
struct GArgs {
    const float* A0; const float* A1;
    const float* B0; const float* B1;
    float* C0; float* C1;
    const float* bias0; const float* bias1;
    int M0, M1, K;
};

template <int RELU, int ACCUM, int ROWFLAG>
__global__ __launch_bounds__(512) void gemm_k(GArgs g) {
    extern __shared__ float smem[];
    const int z = blockIdx.z;
    const float* A    = z ? g.A1 : g.A0;
    const float* B    = z ? g.B1 : g.B0;
    float*       C    = z ? g.C1 : g.C0;
    const float* bias = z ? g.bias1 : g.bias0;
    const int M = z ? g.M1 : g.M0;
    const int K = g.K;

    const int m0 = blockIdx.y * 32;
    if (m0 >= M) return;
    const int n0 = blockIdx.x * 64;

    const int tid  = threadIdx.x;
    const int half = tid >> 8;            // K-half this thread works on
    const int t    = tid & 255;
    const int tx = t & 15, ty = t >> 4;            // compute map: 2 rows, 4 cols
    const int lr = t & 31, lc4 = (t >> 5) & 3;     // A staging (t<128)
    const int bk = t >> 4, bn4 = t & 15;           // B staging (all 256)

    const int K2    = K >> 1;
    const int kbase = half * K2;

    float* As  = smem + half * K2 * 32;            // As[k][m] = k*32+m
    float* Bs  = smem + 2 * K2 * 32 + half * K2 * 64;   // Bs[k][n] = k*64+n
    float* red = smem + 2 * K2 * 96;               // 2048 floats

    // ---- stage the full K-half; all loads independent (high MLP) ----
    if (t < 128) {
#pragma unroll 4
        for (int i = 0; i < K2 / 16; i++) {
            const int kc = 16 * i + 4 * lc4;
            float4 av = *(const float4*)(A + (m0 + lr) * K + kbase + kc);
            As[(kc + 0) * 32 + lr] = av.x;
            As[(kc + 1) * 32 + lr] = av.y;
            As[(kc + 2) * 32 + lr] = av.z;
            As[(kc + 3) * 32 + lr] = av.w;
        }
    }
#pragma unroll 8
    for (int i = 0; i < K2 / 16; i++) {
        const int kr = 16 * i + bk;
        *(float4*)&Bs[kr * 64 + 4 * bn4] =
            *(const float4*)(B + (kbase + kr) * HDIM + n0 + 4 * bn4);
    }
    __syncthreads();

    // ---- barrier-free mainloop ----
    float acc[2][4] = {};
    const float* Ap = As + ty * 2;
    const float* Bp = Bs + tx * 4;
    for (int k0 = 0; k0 < K2; k0 += 16) {
#pragma unroll
        for (int kk = 0; kk < 16; kk++) {
            float2 a2 = *(const float2*)(Ap + (k0 + kk) * 32);
            float4 b4 = *(const float4*)(Bp + (k0 + kk) * 64);
            float a[2] = {a2.x, a2.y};
            float b[4] = {b4.x, b4.y, b4.z, b4.w};
#pragma unroll
            for (int r = 0; r < 2; r++)
#pragma unroll
                for (int c = 0; c < 4; c++) acc[r][c] += a[r] * b[c];
        }
    }

    // ---- deterministic cross-half reduction + epilogue ----
    __syncthreads();
    if (half == 1) {
        *(float4*)&red[t * 8 + 0] = make_float4(acc[0][0], acc[0][1], acc[0][2], acc[0][3]);
        *(float4*)&red[t * 8 + 4] = make_float4(acc[1][0], acc[1][1], acc[1][2], acc[1][3]);
    }
    __syncthreads();
    if (half == 1) return;

    {
        float4 r0 = *(const float4*)&red[t * 8 + 0];
        float4 r1 = *(const float4*)&red[t * 8 + 4];
        acc[0][0] += r0.x; acc[0][1] += r0.y; acc[0][2] += r0.z; acc[0][3] += r0.w;
        acc[1][0] += r1.x; acc[1][1] += r1.y; acc[1][2] += r1.z; acc[1][3] += r1.w;
    }

    const int m = m0 + ty * 2;
    const int n = n0 + tx * 4;
    float bb[4] = {0.f, 0.f, 0.f, 0.f};
    if (bias) {
        bb[0] = bias[n]; bb[1] = bias[n + 1]; bb[2] = bias[n + 2]; bb[3] = bias[n + 3];
    }
#pragma unroll
    for (int r = 0; r < 2; r++) {
        const float fl = ROWFLAG ? g_flag[m + r] : 1.0f;
        float v[4];
#pragma unroll
        for (int c = 0; c < 4; c++) v[c] = acc[r][c] + bb[c] * fl;
        if (ACCUM) {
            float4 cv = *(const float4*)(C + (m + r) * HDIM + n);
            v[0] += cv.x; v[1] += cv.y; v[2] += cv.z; v[3] += cv.w;
        }
        if (RELU) {
#pragma unroll
            for (int c = 0; c < 4; c++) v[c] = fmaxf(v[c], 0.f);
        }
        *(float4*)(C + (m + r) * HDIM + n) = make_float4(v[0], v[1], v[2], v[3]);
    }
}

// ---------------- per-support-point class counts ----------------
__global__ void cnt_k(const int* __restrict__ y) {
    __shared__ int ys[SN];
    int t = threadIdx.x;          // 512 threads
    ys[t] = y[t];
    __syncthreads();
    int yi = ys[t];
    int c = 0;
    for (int j = 0; j < SN; j++) c += (ys[j] == yi);
    c -= 1;                        // exclude self
    g_rdenom[t] = 1.0f / fmaxf((float)c, 1.0f);
    g_flag[t]   = (c > 0) ? 1.0f : 0.0f;
}

// ---------------- masked relu-sum aggregation ----------------
// Hagg[i] = (1/denom_i) * sum_{j: y_j==y_i, j!=i} relu(A[i] + B[j] + bm1t)
__global__ __launch_bounds__(256) void hagg_k(const int* __restrict__ y,
                                              const float* __restrict__ bm1t) {
    const int i = blockIdx.x;
    __shared__ int   ys[SN];
    __shared__ short list[SN];
    __shared__ int   s_cnt;

    const int t = threadIdx.x;     // 256 threads
    ys[t]       = y[t];
    ys[t + 256] = y[t + 256];
    __syncthreads();

    const int yi = ys[i];
    if (t < 32) {                  // warp 0 builds a deterministic, ascending list
        int cnt = 0;
        for (int it = 0; it < SN / 32; it++) {
            int j = it * 32 + t;
            bool m = (ys[j] == yi) && (j != i);
            unsigned mask = __ballot_sync(0xffffffffu, m);
            if (m) {
                int pos = cnt + __popc(mask & ((1u << t) - 1u));
                list[pos] = (short)j;
            }
            cnt += __popc(mask);
        }
        if (t == 0) s_cnt = cnt;
    }
    __syncthreads();

    const int cnt = s_cnt;
    const float ai = g_A[i * HDIM + t] + bm1t[t];
    float acc = 0.f;
    int l = 0;
    for (; l + 4 <= cnt; l += 4) {           // MLP=4 against L2 latency
        int j0 = list[l], j1 = list[l + 1], j2 = list[l + 2], j3 = list[l + 3];
        float v0 = g_Bm[j0 * HDIM + t];
        float v1 = g_Bm[j1 * HDIM + t];
        float v2 = g_Bm[j2 * HDIM + t];
        float v3 = g_Bm[j3 * HDIM + t];
        acc += fmaxf(ai + v0, 0.f);
        acc += fmaxf(ai + v1, 0.f);
        acc += fmaxf(ai + v2, 0.f);
        acc += fmaxf(ai + v3, 0.f);
    }
    for (; l < cnt; l++) {
        int j = list[l];
        acc += fmaxf(ai + g_Bm[j * HDIM + t], 0.f);
    }
    g_Hagg[i * HDIM + t] = acc * g_rdenom[i];
}

// ---------------- final relation scores ----------------
// scores[i][j] = sum_h relu(hq[i][h] + hs[j][h]) * wr2[h] + br2
// 32x64 tile, 512 threads, split-K halves, full K-half staged, barrier-free loop.
__global__ __launch_bounds__(512) void scores_k(const float* __restrict__ wr2,
                                                const float* __restrict__ br2p,
                                                float* __restrict__ out) {
    extern __shared__ float smem[];
    const int m0 = blockIdx.y * 32;   // query rows
    const int n0 = blockIdx.x * 64;   // support cols
    const int tid  = threadIdx.x;
    const int half = tid >> 8;
    const int t    = tid & 255;
    const int tx = t & 15, ty = t >> 4;
    const int lr = t & 31, lc4 = (t >> 5) & 3;   // hq staging (t<128)
    const int jr = t & 63, jc4 = t >> 6;         // hs staging (all 256)

    const int K2    = HDIM / 2;   // 128
    const int kbase = half * K2;

    float* As  = smem + half * K2 * 32;
    float* Bs  = smem + 2 * K2 * 32 + half * K2 * 64;
    float* ws  = smem + 2 * K2 * 96 + half * K2;
    float* red = smem + 2 * K2 * 96 + 2 * K2;

    if (t < 128) {
#pragma unroll 4
        for (int i = 0; i < K2 / 16; i++) {
            const int kc = 16 * i + 4 * lc4;
            float4 av = *(const float4*)(g_hq + (m0 + lr) * HDIM + kbase + kc);
            As[(kc + 0) * 32 + lr] = av.x;
            As[(kc + 1) * 32 + lr] = av.y;
            As[(kc + 2) * 32 + lr] = av.z;
            As[(kc + 3) * 32 + lr] = av.w;
        }
    }
#pragma unroll 8
    for (int i = 0; i < K2 / 16; i++) {
        const int kc = 16 * i + 4 * jc4;
        float4 bv = *(const float4*)(g_hs + (n0 + jr) * HDIM + kbase + kc);
        Bs[(kc + 0) * 64 + jr] = bv.x;
        Bs[(kc + 1) * 64 + jr] = bv.y;
        Bs[(kc + 2) * 64 + jr] = bv.z;
        Bs[(kc + 3) * 64 + jr] = bv.w;
    }
    if (t < K2) ws[t] = wr2[kbase + t];
    __syncthreads();

    float acc[2][4] = {};
    const float* Ap = As + ty * 2;
    const float* Bp = Bs + tx * 4;
    for (int k0 = 0; k0 < K2; k0 += 16) {
#pragma unroll
        for (int kk = 0; kk < 16; kk++) {
            const float w = ws[k0 + kk];
            float2 a2 = *(const float2*)(Ap + (k0 + kk) * 32);
            float4 b4 = *(const float4*)(Bp + (k0 + kk) * 64);
            float a[2] = {a2.x, a2.y};
            float b[4] = {b4.x, b4.y, b4.z, b4.w};
#pragma unroll
            for (int r = 0; r < 2; r++)
#pragma unroll
                for (int c = 0; c < 4; c++)
                    acc[r][c] += fmaxf(a[r] + b[c], 0.f) * w;
        }
    }

    __syncthreads();
    if (half == 1) {
        *(float4*)&red[t * 8 + 0] = make_float4(acc[0][0], acc[0][1], acc[0][2], acc[0][3]);
        *(float4*)&red[t * 8 + 4] = make_float4(acc[1][0], acc[1][1], acc[1][2], acc[1][3]);
    }
    __syncthreads();
    if (half == 1) return;

    {
        float4 r0 = *(const float4*)&red[t * 8 + 0];
        float4 r1 = *(const float4*)&red[t * 8 + 4];
        acc[0][0] += r0.x; acc[0][1] += r0.y; acc[0][2] += r0.z; acc[0][3] += r0.w;
        acc[1][0] += r1.x; acc[1][1] += r1.y; acc[1][2] += r1.z; acc[1][3] += r1.w;
    }

    const float br2 = br2p[0];
    const int m = m0 + ty * 2;
    const int n = n0 + tx * 4;
#pragma unroll
    for (int r = 0; r < 2; r++) {
        *(float4*)(out + (m + r) * SN + n) =
            make_float4(acc[r][0] + br2, acc[r][1] + br2, acc[r][2] + br2, acc[r][3] + br2);
    }
}

// ---------------- host launcher ----------------
static inline int gemm_smem_bytes(int K) {
    const int K2 = K / 2;
    return (2 * K2 * 96 + 2048) * (int)sizeof(float);
}

extern "C" void kernel_launch(void* const* d_in, const int* in_sizes, int n_in,
                              void* d_out, int out_size) {
    (void)in_sizes; (void)n_in; (void)out_size;
    const float* qf  = (const float*)d_in[0];
    const float* sf  = (const float*)d_in[1];
    const int*   y   = (const int*)  d_in[2];
    const float* Wn1 = (const float*)d_in[3];
    const float* bn1 = (const float*)d_in[4];
    const float* Wn2 = (const float*)d_in[5];
    const float* bn2 = (const float*)d_in[6];
    const float* Wm1 = (const float*)d_in[7];
    const float* bm1 = (const float*)d_in[8];
    const float* Wm2 = (const float*)d_in[9];
    const float* bm2 = (const float*)d_in[10];
    const float* Wr1 = (const float*)d_in[11];
    const float* br1 = (const float*)d_in[12];
    const float* wr2 = (const float*)d_in[13];
    const float* br2 = (const float*)d_in[14];
    float* out = (float*)d_out;

    float *tmp, *enc, *Abuf, *Bbuf, *Hg, *hq, *hs;
    cudaGetSymbolAddress((void**)&tmp,  g_tmp);
    cudaGetSymbolAddress((void**)&enc,  g_enc);
    cudaGetSymbolAddress((void**)&Abuf, g_A);
    cudaGetSymbolAddress((void**)&Bbuf, g_Bm);
    cudaGetSymbolAddress((void**)&Hg,   g_Hagg);
    cudaGetSymbolAddress((void**)&hq,   g_hq);
    cudaGetSymbolAddress((void**)&hs,   g_hs);

    // allow big dynamic smem (idempotent; host-side, not captured)
    const int smem512 = gemm_smem_bytes(EDIM);   // 204800
    const int smem256 = gemm_smem_bytes(HDIM);   // 106496
    const int smemSc  = (2 * 128 * 96 + 2 * 128 + 2048) * (int)sizeof(float); // 107520
    cudaFuncSetAttribute(gemm_k<1, 0, 0>, cudaFuncAttributeMaxDynamicSharedMemorySize, smem512);
    cudaFuncSetAttribute(gemm_k<0, 0, 0>, cudaFuncAttributeMaxDynamicSharedMemorySize, smem256);
    cudaFuncSetAttribute(gemm_k<0, 1, 1>, cudaFuncAttributeMaxDynamicSharedMemorySize, smem256);
    cudaFuncSetAttribute(scores_k,        cudaFuncAttributeMaxDynamicSharedMemorySize, smemSc);

    float* qenc = enc;                 // rows [0, 1024)
    float* senc = enc + QN * HDIM;     // rows [1024, 1536)

    // class counts (once)
    cnt_k<<<1, SN>>>(y);

    // encoder layer 1: relu([Qf;Sf] @ Wn1 + bn1) -> g_tmp   (fused q/s via z)
    {
        GArgs a = {qf, sf, Wn1, Wn1, tmp, tmp + QN * HDIM, bn1, bn1, QN, SN, EDIM};
        gemm_k<1, 0, 0><<<dim3(HDIM / 64, QN / 32, 2), 512, smem512>>>(a);
    }
    // encoder layer 2: g_tmp @ Wn2 + bn2 -> g_enc  (single 1536-row GEMM)
    {
        GArgs a = {tmp, nullptr, Wn2, nullptr, enc, nullptr, bn2, nullptr, QN + SN, 0, HDIM};
        gemm_k<0, 0, 0><<<dim3(HDIM / 64, (QN + SN) / 32, 1), 512, smem256>>>(a);
    }

    // message-passing steps
    for (int t = 0; t < NSTEP; t++) {
        const float* Wm1t = Wm1 + (size_t)t * 2 * HDIM * HDIM;
        const float* Wm2t = Wm2 + (size_t)t * HDIM * HDIM;
        const float* bm1t = bm1 + (size_t)t * HDIM;
        const float* bm2t = bm2 + (size_t)t * HDIM;

        // A = s @ W1a ; B = s @ W1b   (fused via z)
        {
            GArgs a = {senc, senc, Wm1t, Wm1t + HDIM * HDIM, Abuf, Bbuf,
                       nullptr, nullptr, SN, SN, HDIM};
            gemm_k<0, 0, 0><<<dim3(HDIM / 64, SN / 32, 2), 512, smem256>>>(a);
        }
        // masked relu aggregation (pre-divided by denom)
        hagg_k<<<SN, HDIM>>>(y, bm1t);
        // s += Hagg @ Wm2t + flag_i * bm2t
        {
            GArgs a = {Hg, nullptr, Wm2t, nullptr, senc, nullptr, bm2t, nullptr,
                       SN, 0, HDIM};
            gemm_k<0, 1, 1><<<dim3(HDIM / 64, SN / 32, 1), 512, smem256>>>(a);
        }
    }

    // relation head: hq = q @ Wr1a + br1 ; hs = s @ Wr1b   (fused via z)
    {
        GArgs a = {qenc, senc, Wr1, Wr1 + HDIM * HDIM, hq, hs, br1, nullptr,
                   QN, SN, HDIM};
        gemm_k<0, 0, 0><<<dim3(HDIM / 64, QN / 32, 2), 512, smem256>>>(a);
    }

    // scores
    scores_k<<<dim3(SN / 64, QN / 32, 1), 512, smemSc>>>(wr2, br2, out);
}

// round 15
// speedup vs baseline: 1.5052x; 1.5052x over previous
#include <cuda_runtime.h>

#define EDIM 512
#define HDIM 256
#define QN   1024
#define SN   512
#define NSTEP 3

// ---------------- scratch (no allocations allowed) ----------------
__device__ float g_tmp[(QN + SN) * HDIM];   // hidden of encoder MLP
__device__ float g_enc[(QN + SN) * HDIM];   // q rows [0,1024), s rows [1024,1536)
__device__ float g_A[SN * HDIM];
__device__ float g_Bm[SN * HDIM];
__device__ float g_Hagg[SN * HDIM];
__device__ float g_hq[QN * HDIM];
__device__ float g_hs[SN * HDIM];
__device__ float g_rdenom[SN];
__device__ float g_flag[SN];

__device__ __forceinline__ void half_bar(int half) {
    // decoupled 256-thread barrier per K-half (tids 0-255 / 256-511)
    asm volatile("bar.sync %0, %1;" :: "r"(half + 1), "r"(256) : "memory");
}

// ---------------- generic fp32 GEMM: C = A(MxK) @ B(KxN=256) ----------------
// 32x64 block tile, 512 threads, intra-block split-K (2 independent halves),
// double-buffered smem (1 barrier / k-tile), 2x4 micro-tile,
// register-pipelined smem operands (LDS for kk+1 issued before FFMA of kk).
struct GArgs {
    const float* A0; const float* A1;
    const float* B0; const float* B1;
    float* C0; float* C1;
    const float* bias0; const float* bias1;
    int M0, M1, K;
};

template <int RELU, int ACCUM, int ROWFLAG>
__global__ __launch_bounds__(512) void gemm_k(GArgs g) {
    const int z = blockIdx.z;
    const float* A    = z ? g.A1 : g.A0;
    const float* B    = z ? g.B1 : g.B0;
    float*       C    = z ? g.C1 : g.C0;
    const float* bias = z ? g.bias1 : g.bias0;
    const int M = z ? g.M1 : g.M0;
    const int K = g.K;

    const int m0 = blockIdx.y * 32;
    if (m0 >= M) return;
    const int n0 = blockIdx.x * 64;

    __shared__ float As[2][2][16][32];   // [half][buf][k][m]
    __shared__ float Bs[2][2][16][64];   // [half][buf][k][n]
    __shared__ float red[256 * 8];       // partial-acc exchange

    const int tid  = threadIdx.x;
    const int half = tid >> 8;            // K-half this thread works on
    const int t    = tid & 255;
    const int tx = t & 15, ty = t >> 4;            // compute map: 2 rows, 4 cols
    const int lr = t & 31, lc4 = (t >> 5) & 3;     // A-tile load (t<128)
    const int bk = t >> 4, bn4 = t & 15;           // B-tile load (all 256)

    const int K2     = K >> 1;
    const int kbase  = half * K2;
    const int ntiles = K2 >> 4;

    // prologue: tile 0 -> buf 0
    {
        float4 av = make_float4(0.f, 0.f, 0.f, 0.f);
        if (t < 128) av = *(const float4*)(A + (m0 + lr) * K + kbase + 4 * lc4);
        float4 bv = *(const float4*)(B + (kbase + bk) * HDIM + n0 + 4 * bn4);
        if (t < 128) {
            As[half][0][4 * lc4 + 0][lr] = av.x;
            As[half][0][4 * lc4 + 1][lr] = av.y;
            As[half][0][4 * lc4 + 2][lr] = av.z;
            As[half][0][4 * lc4 + 3][lr] = av.w;
        }
        *(float4*)&Bs[half][0][bk][4 * bn4] = bv;
        half_bar(half);
    }

    float acc[2][4] = {};

    for (int it = 0; it < ntiles; it++) {
        const int buf = it & 1;

        // prefetch tile it+1 globals into registers (hides L2 latency)
        float4 av2 = make_float4(0.f, 0.f, 0.f, 0.f);
        float4 bv2 = make_float4(0.f, 0.f, 0.f, 0.f);
        const bool more = (it + 1 < ntiles);
        if (more) {
            const int k0 = kbase + (it + 1) * 16;
            if (t < 128) av2 = *(const float4*)(A + (m0 + lr) * K + k0 + 4 * lc4);
            bv2 = *(const float4*)(B + (k0 + bk) * HDIM + n0 + 4 * bn4);
        }

        // register-pipelined smem mainloop
        float2 a_cur = *(const float2*)&As[half][buf][0][ty * 2];
        float4 b_cur = *(const float4*)&Bs[half][buf][0][tx * 4];
#pragma unroll
        for (int kk = 0; kk < 16; kk++) {
            float2 a_nxt = a_cur;
            float4 b_nxt = b_cur;
            if (kk < 15) {
                a_nxt = *(const float2*)&As[half][buf][kk + 1][ty * 2];
                b_nxt = *(const float4*)&Bs[half][buf][kk + 1][tx * 4];
            }
            float a[2] = {a_cur.x, a_cur.y};
            float b[4] = {b_cur.x, b_cur.y, b_cur.z, b_cur.w};
#pragma unroll
            for (int r = 0; r < 2; r++)
#pragma unroll
                for (int c = 0; c < 4; c++) acc[r][c] += a[r] * b[c];
            a_cur = a_nxt;
            b_cur = b_nxt;
        }

        if (more) {
            const int nb = buf ^ 1;
            if (t < 128) {
                As[half][nb][4 * lc4 + 0][lr] = av2.x;
                As[half][nb][4 * lc4 + 1][lr] = av2.y;
                As[half][nb][4 * lc4 + 2][lr] = av2.z;
                As[half][nb][4 * lc4 + 3][lr] = av2.w;
            }
            *(float4*)&Bs[half][nb][bk][4 * bn4] = bv2;
            half_bar(half);
        }
    }

    // deterministic cross-half reduction: half1 stores, half0 adds
    __syncthreads();
    if (half == 1) {
        *(float4*)&red[t * 8 + 0] = make_float4(acc[0][0], acc[0][1], acc[0][2], acc[0][3]);
        *(float4*)&red[t * 8 + 4] = make_float4(acc[1][0], acc[1][1], acc[1][2], acc[1][3]);
    }
    __syncthreads();
    if (half == 1) return;

    {
        float4 r0 = *(const float4*)&red[t * 8 + 0];
        float4 r1 = *(const float4*)&red[t * 8 + 4];
        acc[0][0] += r0.x; acc[0][1] += r0.y; acc[0][2] += r0.z; acc[0][3] += r0.w;
        acc[1][0] += r1.x; acc[1][1] += r1.y; acc[1][2] += r1.z; acc[1][3] += r1.w;
    }

    const int m = m0 + ty * 2;
    const int n = n0 + tx * 4;
    float bb[4] = {0.f, 0.f, 0.f, 0.f};
    if (bias) {
        bb[0] = bias[n]; bb[1] = bias[n + 1]; bb[2] = bias[n + 2]; bb[3] = bias[n + 3];
    }
#pragma unroll
    for (int r = 0; r < 2; r++) {
        const float fl = ROWFLAG ? g_flag[m + r] : 1.0f;
        float v[4];
#pragma unroll
        for (int c = 0; c < 4; c++) v[c] = acc[r][c] + bb[c] * fl;
        if (ACCUM) {
            float4 cv = *(const float4*)(C + (m + r) * HDIM + n);
            v[0] += cv.x; v[1] += cv.y; v[2] += cv.z; v[3] += cv.w;
        }
        if (RELU) {
#pragma unroll
            for (int c = 0; c < 4; c++) v[c] = fmaxf(v[c], 0.f);
        }
        *(float4*)(C + (m + r) * HDIM + n) = make_float4(v[0], v[1], v[2], v[3]);
    }
}

// ---------------- per-support-point class counts ----------------
__global__ void cnt_k(const int* __restrict__ y) {
    __shared__ int ys[SN];
    int t = threadIdx.x;          // 512 threads
    ys[t] = y[t];
    __syncthreads();
    int yi = ys[t];
    int c = 0;
    for (int j = 0; j < SN; j++) c += (ys[j] == yi);
    c -= 1;                        // exclude self
    g_rdenom[t] = 1.0f / fmaxf((float)c, 1.0f);
    g_flag[t]   = (c > 0) ? 1.0f : 0.0f;
}

// ---------------- masked relu-sum aggregation ----------------
// Hagg[i] = (1/denom_i) * sum_{j: y_j==y_i, j!=i} relu(A[i] + B[j] + bm1t)
__global__ __launch_bounds__(256) void hagg_k(const int* __restrict__ y,
                                              const float* __restrict__ bm1t) {
    const int i = blockIdx.x;
    __shared__ int   ys[SN];
    __shared__ short list[SN];
    __shared__ int   s_cnt;

    const int t = threadIdx.x;     // 256 threads
    ys[t]       = y[t];
    ys[t + 256] = y[t + 256];
    __syncthreads();

    const int yi = ys[i];
    if (t < 32) {                  // warp 0 builds a deterministic, ascending list
        int cnt = 0;
        for (int it = 0; it < SN / 32; it++) {
            int j = it * 32 + t;
            bool m = (ys[j] == yi) && (j != i);
            unsigned mask = __ballot_sync(0xffffffffu, m);
            if (m) {
                int pos = cnt + __popc(mask & ((1u << t) - 1u));
                list[pos] = (short)j;
            }
            cnt += __popc(mask);
        }
        if (t == 0) s_cnt = cnt;
    }
    __syncthreads();

    const int cnt = s_cnt;
    const float ai = g_A[i * HDIM + t] + bm1t[t];
    float acc = 0.f;
    int l = 0;
    for (; l + 4 <= cnt; l += 4) {           // MLP=4 against L2 latency
        int j0 = list[l], j1 = list[l + 1], j2 = list[l + 2], j3 = list[l + 3];
        float v0 = g_Bm[j0 * HDIM + t];
        float v1 = g_Bm[j1 * HDIM + t];
        float v2 = g_Bm[j2 * HDIM + t];
        float v3 = g_Bm[j3 * HDIM + t];
        acc += fmaxf(ai + v0, 0.f);
        acc += fmaxf(ai + v1, 0.f);
        acc += fmaxf(ai + v2, 0.f);
        acc += fmaxf(ai + v3, 0.f);
    }
    for (; l < cnt; l++) {
        int j = list[l];
        acc += fmaxf(ai + g_Bm[j * HDIM + t], 0.f);
    }
    g_Hagg[i * HDIM + t] = acc * g_rdenom[i];
}

// ---------------- final relation scores ----------------
// scores[i][j] = sum_h relu(hq[i][h] + hs[j][h]) * wr2[h] + br2
// 32x64 tile, 512 threads, split-K halves, double-buffered, register-pipelined.
__global__ __launch_bounds__(512) void scores_k(const float* __restrict__ wr2,
                                                const float* __restrict__ br2p,
                                                float* __restrict__ out) {
    __shared__ float As[2][2][16][32];   // [half][buf][k][i]  (hq)
    __shared__ float Bs[2][2][16][64];   // [half][buf][k][j]  (hs)
    __shared__ float ws[2][2][16];
    __shared__ float red[256 * 8];

    const int m0 = blockIdx.y * 32;   // query rows
    const int n0 = blockIdx.x * 64;   // support cols
    const int tid  = threadIdx.x;
    const int half = tid >> 8;
    const int t    = tid & 255;
    const int tx = t & 15, ty = t >> 4;
    const int lr = t & 31, lc4 = (t >> 5) & 3;   // hq load (t<128)
    const int jr = t & 63, jc4 = t >> 6;         // hs load (all 256)

    const int kbase  = half * (HDIM / 2);
    const int ntiles = (HDIM / 2) >> 4;

    // prologue
    {
        float4 av = make_float4(0.f, 0.f, 0.f, 0.f);
        if (t < 128) av = *(const float4*)(g_hq + (m0 + lr) * HDIM + kbase + 4 * lc4);
        float4 bv = *(const float4*)(g_hs + (n0 + jr) * HDIM + kbase + 4 * jc4);
        if (t < 128) {
            As[half][0][4 * lc4 + 0][lr] = av.x;
            As[half][0][4 * lc4 + 1][lr] = av.y;
            As[half][0][4 * lc4 + 2][lr] = av.z;
            As[half][0][4 * lc4 + 3][lr] = av.w;
        }
        Bs[half][0][4 * jc4 + 0][jr] = bv.x;
        Bs[half][0][4 * jc4 + 1][jr] = bv.y;
        Bs[half][0][4 * jc4 + 2][jr] = bv.z;
        Bs[half][0][4 * jc4 + 3][jr] = bv.w;
        if (t < 16) ws[half][0][t] = wr2[kbase + t];
        half_bar(half);
    }

    float acc[2][4] = {};

    for (int it = 0; it < ntiles; it++) {
        const int buf = it & 1;
        float4 av2 = make_float4(0.f, 0.f, 0.f, 0.f);
        float4 bv2 = make_float4(0.f, 0.f, 0.f, 0.f);
        float wv2 = 0.f;
        const bool more = (it + 1 < ntiles);
        if (more) {
            const int k0 = kbase + (it + 1) * 16;
            if (t < 128) av2 = *(const float4*)(g_hq + (m0 + lr) * HDIM + k0 + 4 * lc4);
            bv2 = *(const float4*)(g_hs + (n0 + jr) * HDIM + k0 + 4 * jc4);
            if (t < 16) wv2 = wr2[k0 + t];
        }

        float2 a_cur = *(const float2*)&As[half][buf][0][ty * 2];
        float4 b_cur = *(const float4*)&Bs[half][buf][0][tx * 4];
        float  w_cur = ws[half][buf][0];
#pragma unroll
        for (int kk = 0; kk < 16; kk++) {
            float2 a_nxt = a_cur;
            float4 b_nxt = b_cur;
            float  w_nxt = w_cur;
            if (kk < 15) {
                a_nxt = *(const float2*)&As[half][buf][kk + 1][ty * 2];
                b_nxt = *(const float4*)&Bs[half][buf][kk + 1][tx * 4];
                w_nxt = ws[half][buf][kk + 1];
            }
            float a[2] = {a_cur.x, a_cur.y};
            float b[4] = {b_cur.x, b_cur.y, b_cur.z, b_cur.w};
#pragma unroll
            for (int r = 0; r < 2; r++)
#pragma unroll
                for (int c = 0; c < 4; c++)
                    acc[r][c] += fmaxf(a[r] + b[c], 0.f) * w_cur;
            a_cur = a_nxt; b_cur = b_nxt; w_cur = w_nxt;
        }

        if (more) {
            const int nb = buf ^ 1;
            if (t < 128) {
                As[half][nb][4 * lc4 + 0][lr] = av2.x;
                As[half][nb][4 * lc4 + 1][lr] = av2.y;
                As[half][nb][4 * lc4 + 2][lr] = av2.z;
                As[half][nb][4 * lc4 + 3][lr] = av2.w;
            }
            Bs[half][nb][4 * jc4 + 0][jr] = bv2.x;
            Bs[half][nb][4 * jc4 + 1][jr] = bv2.y;
            Bs[half][nb][4 * jc4 + 2][jr] = bv2.z;
            Bs[half][nb][4 * jc4 + 3][jr] = bv2.w;
            if (t < 16) ws[half][nb][t] = wv2;
            half_bar(half);
        }
    }

    __syncthreads();
    if (half == 1) {
        *(float4*)&red[t * 8 + 0] = make_float4(acc[0][0], acc[0][1], acc[0][2], acc[0][3]);
        *(float4*)&red[t * 8 + 4] = make_float4(acc[1][0], acc[1][1], acc[1][2], acc[1][3]);
    }
    __syncthreads();
    if (half == 1) return;

    {
        float4 r0 = *(const float4*)&red[t * 8 + 0];
        float4 r1 = *(const float4*)&red[t * 8 + 4];
        acc[0][0] += r0.x; acc[0][1] += r0.y; acc[0][2] += r0.z; acc[0][3] += r0.w;
        acc[1][0] += r1.x; acc[1][1] += r1.y; acc[1][2] += r1.z; acc[1][3] += r1.w;
    }

    const float br2 = br2p[0];
    const int m = m0 + ty * 2;
    const int n = n0 + tx * 4;
#pragma unroll
    for (int r = 0; r < 2; r++) {
        *(float4*)(out + (m + r) * SN + n) =
            make_float4(acc[r][0] + br2, acc[r][1] + br2, acc[r][2] + br2, acc[r][3] + br2);
    }
}

// ---------------- host launcher ----------------
extern "C" void kernel_launch(void* const* d_in, const int* in_sizes, int n_in,
                              void* d_out, int out_size) {
    (void)in_sizes; (void)n_in; (void)out_size;
    const float* qf  = (const float*)d_in[0];
    const float* sf  = (const float*)d_in[1];
    const int*   y   = (const int*)  d_in[2];
    const float* Wn1 = (const float*)d_in[3];
    const float* bn1 = (const float*)d_in[4];
    const float* Wn2 = (const float*)d_in[5];
    const float* bn2 = (const float*)d_in[6];
    const float* Wm1 = (const float*)d_in[7];
    const float* bm1 = (const float*)d_in[8];
    const float* Wm2 = (const float*)d_in[9];
    const float* bm2 = (const float*)d_in[10];
    const float* Wr1 = (const float*)d_in[11];
    const float* br1 = (const float*)d_in[12];
    const float* wr2 = (const float*)d_in[13];
    const float* br2 = (const float*)d_in[14];
    float* out = (float*)d_out;

    float *tmp, *enc, *Abuf, *Bbuf, *Hg, *hq, *hs;
    cudaGetSymbolAddress((void**)&tmp,  g_tmp);
    cudaGetSymbolAddress((void**)&enc,  g_enc);
    cudaGetSymbolAddress((void**)&Abuf, g_A);
    cudaGetSymbolAddress((void**)&Bbuf, g_Bm);
    cudaGetSymbolAddress((void**)&Hg,   g_Hagg);
    cudaGetSymbolAddress((void**)&hq,   g_hq);
    cudaGetSymbolAddress((void**)&hs,   g_hs);

    float* qenc = enc;                 // rows [0, 1024)
    float* senc = enc + QN * HDIM;     // rows [1024, 1536)

    // class counts (once)
    cnt_k<<<1, SN>>>(y);

    // encoder layer 1: relu([Qf;Sf] @ Wn1 + bn1) -> g_tmp   (fused q/s via z)
    {
        GArgs a = {qf, sf, Wn1, Wn1, tmp, tmp + QN * HDIM, bn1, bn1, QN, SN, EDIM};
        gemm_k<1, 0, 0><<<dim3(HDIM / 64, QN / 32, 2), 512>>>(a);
    }
    // encoder layer 2: g_tmp @ Wn2 + bn2 -> g_enc  (single 1536-row GEMM)
    {
        GArgs a = {tmp, nullptr, Wn2, nullptr, enc, nullptr, bn2, nullptr, QN + SN, 0, HDIM};
        gemm_k<0, 0, 0><<<dim3(HDIM / 64, (QN + SN) / 32, 1), 512>>>(a);
    }

    // message-passing steps
    for (int t = 0; t < NSTEP; t++) {
        const float* Wm1t = Wm1 + (size_t)t * 2 * HDIM * HDIM;
        const float* Wm2t = Wm2 + (size_t)t * HDIM * HDIM;
        const float* bm1t = bm1 + (size_t)t * HDIM;
        const float* bm2t = bm2 + (size_t)t * HDIM;

        // A = s @ W1a ; B = s @ W1b   (fused via z)
        {
            GArgs a = {senc, senc, Wm1t, Wm1t + HDIM * HDIM, Abuf, Bbuf,
                       nullptr, nullptr, SN, SN, HDIM};
            gemm_k<0, 0, 0><<<dim3(HDIM / 64, SN / 32, 2), 512>>>(a);
        }
        // masked relu aggregation (pre-divided by denom)
        hagg_k<<<SN, HDIM>>>(y, bm1t);
        // s += Hagg @ Wm2t + flag_i * bm2t
        {
            GArgs a = {Hg, nullptr, Wm2t, nullptr, senc, nullptr, bm2t, nullptr,
                       SN, 0, HDIM};
            gemm_k<0, 1, 1><<<dim3(HDIM / 64, SN / 32, 1), 512>>>(a);
        }
    }

    // relation head: hq = q @ Wr1a + br1 ; hs = s @ Wr1b   (fused via z)
    {
        GArgs a = {qenc, senc, Wr1, Wr1 + HDIM * HDIM, hq, hs, br1, nullptr,
                   QN, SN, HDIM};
        gemm_k<0, 0, 0><<<dim3(HDIM / 64, QN / 32, 2), 512>>>(a);
    }

    // scores
    scores_k<<<dim3(SN / 64, QN / 32, 1), 512>>>(wr2, br2, out);
}